// round 4
// baseline (speedup 1.0000x reference)
#include <cuda_runtime.h>
#include <cuda_bf16.h>
#include <cstdint>

#define N_MAX 100000
#define E_MAX 1600000

// ---------------- static device scratch (no allocations allowed) -------------
__device__ unsigned g_hb[(size_t)N_MAX * 32]; // h in bf16x2 (64 bf16 per node)
__device__ float g_as[N_MAX];                 // a_src per node
__device__ float g_ad[N_MAX];                 // a_dst per node
__device__ int   g_count[N_MAX];              // in-degree histogram
__device__ int   g_off[N_MAX];                // exclusive offsets
__device__ int   g_cur[N_MAX];                // scatter cursors
__device__ int   g_part[256];                 // scan block partials
__device__ int2  g_edge[E_MAX];               // decoded (src,dst) per edge
__device__ int   g_srt[E_MAX];                // edge sources binned by dst
__device__ float g_rsum[64];                  // sum over nodes of relu(agg)
__device__ int   g_is64;                      // 1 if edge buffer is int64 words

// ---------------- kernel 0: zero scratch + detect edge width -----------------
// int64 values < 2^31 have all-zero odd words (LE); int32 node ids don't.
__global__ void k_init(const int* __restrict__ ei32, int E, int n) {
    int i = blockIdx.x * blockDim.x + threadIdx.x;
    if (i < n) g_count[i] = 0;
    if (i < 64) g_rsum[i] = 0.f;
    if (blockIdx.x == 0 && threadIdx.x < 32) {
        int nz = 0;
        int samples = 2048 < E ? 2048 : E;
        for (int e = (int)threadIdx.x; e < samples; e += 32)
            nz |= ei32[2 * e + 1];
#pragma unroll
        for (int o = 16; o > 0; o >>= 1)
            nz |= __shfl_xor_sync(0xffffffffu, nz, o);
        if (threadIdx.x == 0) g_is64 = (nz == 0) ? 1 : 0;
    }
}

// ---------------- kernel 1: GEMM h = x@W (f32x2 FFMA), a_src/a_dst, bf16 h ---
// One node per thread. W staged in smem as ulonglong2 so each 16B LDS yields
// two aligned b64 f32-pairs consumed directly by fma.rn.f32x2 (no repack movs).
__global__ void __launch_bounds__(128) k_gemm(
    const float* __restrict__ x, const float* __restrict__ W,
    const float* __restrict__ att_s, const float* __restrict__ att_d, int n)
{
    __shared__ ulonglong2 Ws[2048];   // 128 rows x 16 ulonglong2 (32KB)
    __shared__ float atts[64], attd[64];
    int t = threadIdx.x;
    for (int i = t; i < 2048; i += 128) Ws[i] = ((const ulonglong2*)W)[i];
    if (t < 64) { atts[t] = att_s[t]; attd[t] = att_d[t]; }
    __syncthreads();

    int node = blockIdx.x * 128 + t;
    if (node >= n) return;

    const float4* xr = (const float4*)(x + (size_t)node * 128);
    unsigned long long acc2[32];
    {
        float z = 0.f;
        unsigned long long zp;
        asm("mov.b64 %0, {%1,%1};" : "=l"(zp) : "f"(z));
#pragma unroll
        for (int c = 0; c < 32; c++) acc2[c] = zp;
    }

#pragma unroll 1
    for (int k4 = 0; k4 < 32; k4++) {
        float4 xq = xr[k4];
        float xa[4];
        xa[0] = xq.x; xa[1] = xq.y; xa[2] = xq.z; xa[3] = xq.w;
#pragma unroll
        for (int i = 0; i < 4; i++) {
            unsigned long long xp;
            asm("mov.b64 %0, {%1,%1};" : "=l"(xp) : "f"(xa[i]));
            int kk = k4 * 4 + i;
#pragma unroll
            for (int c = 0; c < 16; c++) {
                ulonglong2 w = Ws[kk * 16 + c];   // broadcast LDS.128
                asm("fma.rn.f32x2 %0, %1, %2, %0;" : "+l"(acc2[2*c])   : "l"(xp), "l"(w.x));
                asm("fma.rn.f32x2 %0, %1, %2, %0;" : "+l"(acc2[2*c+1]) : "l"(xp), "l"(w.y));
            }
        }
    }

    float s = 0.f, d = 0.f;
    unsigned hb[32];
#pragma unroll
    for (int c = 0; c < 32; c++) {
        float lo, hi;
        asm("mov.b64 {%0,%1}, %2;" : "=f"(lo), "=f"(hi) : "l"(acc2[c]));
        s += lo * atts[2*c] + hi * atts[2*c+1];
        d += lo * attd[2*c] + hi * attd[2*c+1];
        __nv_bfloat162 b = __floats2bfloat162_rn(lo, hi);
        hb[c] = *reinterpret_cast<unsigned*>(&b);
    }
    uint4* out4 = (uint4*)(g_hb + (size_t)node * 32);
#pragma unroll
    for (int q = 0; q < 8; q++)
        out4[q] = make_uint4(hb[4*q], hb[4*q+1], hb[4*q+2], hb[4*q+3]);
    g_as[node] = s;
    g_ad[node] = d;
}

// ---------------- kernel 2: decode edges (vectorized) + dst histogram --------
// Reads 2 edges per thread; writes compact (src,dst) pairs for the scatter.
__global__ void k_edges(const int* __restrict__ ei32, int E, int n) {
    int t2 = blockIdx.x * blockDim.x + threadIdx.x;
    int e = t2 * 2;
    if (e >= E) return;
    int is64 = g_is64;
    int s0, d0, s1 = -1, d1 = -1;
    bool two = (e + 1 < E);
    if (((E & 1) == 0) && two) {
        if (is64) {
            const longlong2* sp = (const longlong2*)ei32;
            longlong2 sv = sp[t2];
            longlong2 dv = sp[(E >> 1) + t2];
            s0 = (int)sv.x; s1 = (int)sv.y; d0 = (int)dv.x; d1 = (int)dv.y;
        } else {
            const int2* sp = (const int2*)ei32;
            int2 sv = sp[t2];
            int2 dv = sp[(E >> 1) + t2];
            s0 = sv.x; s1 = sv.y; d0 = dv.x; d1 = dv.y;
        }
    } else {
        if (is64) {
            s0 = ei32[2 * (size_t)e];
            d0 = ei32[2 * ((size_t)E + e)];
            if (two) { s1 = ei32[2 * (size_t)(e+1)]; d1 = ei32[2 * ((size_t)E + e + 1)]; }
        } else {
            s0 = ei32[e];
            d0 = ei32[(size_t)E + e];
            if (two) { s1 = ei32[e+1]; d1 = ei32[(size_t)E + e + 1]; }
        }
    }
    bool v0 = (unsigned)s0 < (unsigned)n && (unsigned)d0 < (unsigned)n;
    bool v1 = two && (unsigned)s1 < (unsigned)n && (unsigned)d1 < (unsigned)n;
    g_edge[e] = make_int2(s0, v0 ? d0 : -1);
    if (two) g_edge[e+1] = make_int2(s1, v1 ? d1 : -1);
    if (v0) atomicAdd(&g_count[d0], 1);
    if (v1) atomicAdd(&g_count[d1], 1);
}

// ---------------- kernels 3-5: two-level exclusive scan ----------------------
__global__ void k_scan1(int n) {
    __shared__ int sm[1024];
    int tid = threadIdx.x;
    int gid = blockIdx.x * 1024 + tid;
    int v = (gid < n) ? g_count[gid] : 0;
    sm[tid] = v;
    __syncthreads();
    for (int off = 1; off < 1024; off <<= 1) {
        int add = 0;
        if (tid >= off) add = sm[tid - off];
        __syncthreads();
        sm[tid] += add;
        __syncthreads();
    }
    int incl = sm[tid];
    if (gid < n) g_off[gid] = incl - v;
    if (tid == 1023) g_part[blockIdx.x] = incl;
}

__global__ void k_scan2(int nb) {
    __shared__ int sm[256];
    int tid = threadIdx.x;
    int v = (tid < nb) ? g_part[tid] : 0;
    sm[tid] = v;
    __syncthreads();
    for (int off = 1; off < 256; off <<= 1) {
        int add = 0;
        if (tid >= off) add = sm[tid - off];
        __syncthreads();
        sm[tid] += add;
        __syncthreads();
    }
    if (tid < nb) g_part[tid] = sm[tid] - v;
}

__global__ void k_scan3(int n) {
    int i = blockIdx.x * blockDim.x + threadIdx.x;
    if (i < n) {
        int off = g_off[i] + g_part[i >> 10];
        g_off[i] = off;
        g_cur[i] = off;
    }
}

// ---------------- kernel 6: scatter edges binned by dst ----------------------
__global__ void k_scatter(int E) {
    int e = blockIdx.x * blockDim.x + threadIdx.x;
    if (e < E) {
        int2 ed = g_edge[e];
        if (ed.y >= 0) {
            int p = atomicAdd(&g_cur[ed.y], 1);
            g_srt[p] = ed.x;
        }
    }
}

// ---------------- kernel 7: warp-per-node softmax aggregation ----------------
// Chunk 32 edges at a time: lane k loads (j, w) coalesced, shfl-broadcast to
// all lanes for the bf16 h gather (128B per edge). Self loop = virtual edge.
// No max-shift: logits bounded ~|8|, exp safe in fp32, softmax shift-invariant.
__global__ void __launch_bounds__(256) k_agg(const float* __restrict__ bias, int n) {
    __shared__ float rs[64];
    int t = threadIdx.x;
    if (t < 64) rs[t] = 0.f;
    __syncthreads();

    int warp = (blockIdx.x * 256 + t) >> 5;
    int l = t & 31;
    if (warp < n) {
        int i = warp;
        int start = g_off[i];
        int len = g_count[i];
        float adi = g_ad[i];
        float accx = 0.f, accy = 0.f, den = 0.f;
        int total = len + 1;                       // + self loop
        for (int base = 0; base < total; base += 32) {
            int k = base + l;
            int j = i; float wv = 0.f;
            if (k < total) {
                if (k < len) j = g_srt[start + k];  // coalesced
                float v = g_as[j] + adi;
                v = v > 0.f ? v : 0.2f * v;
                wv = __expf(v);
            }
            den += wv;
            int m = total - base; if (m > 32) m = 32;
            for (int kk = 0; kk < m; kk++) {
                int jj   = __shfl_sync(0xffffffffu, j,  kk);
                float w  = __shfl_sync(0xffffffffu, wv, kk);
                unsigned p = g_hb[(size_t)jj * 32 + l];      // coalesced 128B
                float2 hv = __bfloat1622float2(*reinterpret_cast<__nv_bfloat162*>(&p));
                accx += w * hv.x;
                accy += w * hv.y;
            }
        }
#pragma unroll
        for (int o = 16; o > 0; o >>= 1)
            den += __shfl_xor_sync(0xffffffffu, den, o);
        float inv = 1.f / den;
        float r0 = accx * inv + bias[2*l];     r0 = r0 > 0.f ? r0 : 0.f;
        float r1 = accy * inv + bias[2*l+1];   r1 = r1 > 0.f ? r1 : 0.f;
        atomicAdd(&rs[2*l],     r0);
        atomicAdd(&rs[2*l + 1], r1);
    }
    __syncthreads();
    if (t < 64) atomicAdd(&g_rsum[t], rs[t]);
}

// ---------------- kernel 8: out = (rsum/N) @ W_lin + b_lin -------------------
__global__ void k_final(const float* __restrict__ Wl, const float* __restrict__ bl,
                        float* __restrict__ out, float invn) {
    int o = threadIdx.x;   // 64 threads
    float s = 0.f;
#pragma unroll 4
    for (int c = 0; c < 64; c++) s += g_rsum[c] * Wl[c * 64 + o];
    out[o] = s * invn + bl[o];
}

// ---------------- launcher ---------------------------------------------------
extern "C" void kernel_launch(void* const* d_in, const int* in_sizes, int n_in,
                              void* d_out, int out_size) {
    const float* x    = (const float*)d_in[0];
    const int*   ei32 = (const int*)d_in[1];     // int32 OR int64 words (probed)
    const float* W    = (const float*)d_in[2];
    const float* atts = (const float*)d_in[3];
    const float* attd = (const float*)d_in[4];
    const float* bc   = (const float*)d_in[5];
    const float* Wl   = (const float*)d_in[6];
    const float* bl   = (const float*)d_in[7];
    float*       out  = (float*)d_out;

    int n = in_sizes[0] / 128;   // nodes
    int E = in_sizes[1] / 2;     // edges ([2, E] layout)
    if (n > N_MAX) n = N_MAX;
    if (E > E_MAX) E = E_MAX;

    int nb1 = (n + 1023) / 1024;
    int Epairs = (E + 1) / 2;

    k_init   <<<(n + 255) / 256, 256>>>(ei32, E, n);
    k_gemm   <<<(n + 127) / 128, 128>>>(x, W, atts, attd, n);
    k_edges  <<<(Epairs + 255) / 256, 256>>>(ei32, E, n);
    k_scan1  <<<nb1, 1024>>>(n);
    k_scan2  <<<1, 256>>>(nb1);
    k_scan3  <<<(n + 255) / 256, 256>>>(n);
    k_scatter<<<(E + 255) / 256, 256>>>(E);
    k_agg    <<<(n + 7) / 8, 256>>>(bc, n);
    k_final  <<<1, 64>>>(Wl, bl, out, 1.f / (float)n);
}

// round 6
// speedup vs baseline: 1.1064x; 1.1064x over previous
#include <cuda_runtime.h>
#include <cuda_bf16.h>
#include <cstdint>

#define N_MAX 100000
#define E_MAX 1600000

// ---------------- static device scratch (no allocations allowed) -------------
__device__ unsigned g_hb[(size_t)N_MAX * 32]; // h in bf16x2 (64 bf16 per node)
__device__ float g_as[N_MAX];                 // a_src per node
__device__ float g_ad[N_MAX];                 // a_dst per node
__device__ int   g_count[N_MAX];              // in-degree histogram
__device__ int   g_off[N_MAX];                // exclusive offsets
__device__ int   g_cur[N_MAX];                // scatter cursors
__device__ int   g_part[256];                 // scan block partials
__device__ int   g_srt[E_MAX];                // edge sources binned by dst
__device__ float g_rsum[64];                  // sum over nodes of relu(agg)
__device__ int   g_is64;                      // 1 if edge buffer is int64 words
__device__ unsigned g_done;                   // agg completion ticket

// ---------------- kernel 1: zero scratch + detect edge width -----------------
__global__ void k_init(const int* __restrict__ ei32, int E, int n) {
    int i = blockIdx.x * blockDim.x + threadIdx.x;
    if (i < n) g_count[i] = 0;
    if (i < 64) g_rsum[i] = 0.f;
    if (i == 0) g_done = 0u;
    if (blockIdx.x == 0 && threadIdx.x < 32) {
        // int64 values < 2^31 have all-zero odd words (LE); int32 ids don't.
        int nz = 0;
        int samples = 2048 < E ? 2048 : E;
        for (int e = (int)threadIdx.x; e < samples; e += 32)
            nz |= ei32[2 * e + 1];
#pragma unroll
        for (int o = 16; o > 0; o >>= 1)
            nz |= __shfl_xor_sync(0xffffffffu, nz, o);
        if (threadIdx.x == 0) g_is64 = (nz == 0) ? 1 : 0;
    }
}

// ---------------- kernel 2: dst histogram (dst row only, 2 edges/thread) -----
__global__ void k_hist(const int* __restrict__ ei, int E, int n) {
    int t2 = blockIdx.x * blockDim.x + threadIdx.x;
    int e = t2 * 2;
    if (e >= E) return;
    bool two = (e + 1 < E);
    int d0, d1 = -1;
    if (g_is64) {
        if (two && (E & 1) == 0) {
            int4 v = ((const int4*)(ei + 2 * (size_t)E))[t2];
            d0 = v.x; d1 = v.z;
        } else {
            d0 = ei[2 * ((size_t)E + e)];
            if (two) d1 = ei[2 * ((size_t)E + e + 1)];
        }
    } else {
        if (two && (E & 1) == 0) {
            int2 v = ((const int2*)(ei + (size_t)E))[t2];
            d0 = v.x; d1 = v.y;
        } else {
            d0 = ei[(size_t)E + e];
            if (two) d1 = ei[(size_t)E + e + 1];
        }
    }
    if ((unsigned)d0 < (unsigned)n) atomicAdd(&g_count[d0], 1);
    if (two && (unsigned)d1 < (unsigned)n) atomicAdd(&g_count[d1], 1);
}

// ---------------- kernels 3,5,6: two-level exclusive scan (proven) -----------
__global__ void __launch_bounds__(1024) k_scan1(int n) {
    __shared__ int wsum[32];
    int tid = threadIdx.x, lane = tid & 31, wid = tid >> 5;
    int gid = blockIdx.x * 1024 + tid;
    int v = (gid < n) ? g_count[gid] : 0;
    int incl = v;
#pragma unroll
    for (int o = 1; o < 32; o <<= 1) {
        int t = __shfl_up_sync(0xffffffffu, incl, o);
        if (lane >= o) incl += t;
    }
    if (lane == 31) wsum[wid] = incl;
    __syncthreads();
    if (wid == 0) {
        int w = wsum[lane];
#pragma unroll
        for (int o = 1; o < 32; o <<= 1) {
            int t = __shfl_up_sync(0xffffffffu, w, o);
            if (lane >= o) w += t;
        }
        wsum[lane] = w;
    }
    __syncthreads();
    int blk_incl = incl + (wid > 0 ? wsum[wid - 1] : 0);
    if (gid < n) g_off[gid] = blk_incl - v;
    if (tid == 1023) g_part[blockIdx.x] = blk_incl;
}

__global__ void k_scan2(int nb) {
    __shared__ int sm[256];
    int tid = threadIdx.x;
    int v = (tid < nb) ? g_part[tid] : 0;
    sm[tid] = v;
    __syncthreads();
    for (int off = 1; off < 256; off <<= 1) {
        int add = 0;
        if (tid >= off) add = sm[tid - off];
        __syncthreads();
        sm[tid] += add;
        __syncthreads();
    }
    if (tid < nb) g_part[tid] = sm[tid] - v;
}

__global__ void k_scan3(int n) {
    int i = blockIdx.x * blockDim.x + threadIdx.x;
    if (i < n) {
        int off = g_off[i] + g_part[i >> 10];
        g_off[i] = off;
        g_cur[i] = off;
    }
}

// ---------------- kernel 4 (PROFILED SLOT): GEMM h = x@W, f32x2 FFMA ---------
// One node per thread. W staged in smem as ulonglong2: each 16B broadcast LDS
// yields two aligned b64 f32-pairs consumed directly by fma.rn.f32x2.
__global__ void __launch_bounds__(128) k_gemm(
    const float* __restrict__ x, const float* __restrict__ W,
    const float* __restrict__ att_s, const float* __restrict__ att_d, int n)
{
    __shared__ ulonglong2 Ws[2048];   // 128 rows x 16 ulonglong2 (32KB)
    __shared__ float atts[64], attd[64];
    int t = threadIdx.x;
    for (int i = t; i < 2048; i += 128) Ws[i] = ((const ulonglong2*)W)[i];
    if (t < 64) { atts[t] = att_s[t]; attd[t] = att_d[t]; }
    __syncthreads();

    int node = blockIdx.x * 128 + t;
    if (node >= n) return;

    const float4* xr = (const float4*)(x + (size_t)node * 128);
    unsigned long long acc2[32];
    {
        float z = 0.f;
        unsigned long long zp;
        asm("mov.b64 %0, {%1,%1};" : "=l"(zp) : "f"(z));
#pragma unroll
        for (int c = 0; c < 32; c++) acc2[c] = zp;
    }

#pragma unroll 1
    for (int k4 = 0; k4 < 32; k4++) {
        float4 xq = xr[k4];
        float xa[4];
        xa[0] = xq.x; xa[1] = xq.y; xa[2] = xq.z; xa[3] = xq.w;
#pragma unroll
        for (int i = 0; i < 4; i++) {
            unsigned long long xp;
            asm("mov.b64 %0, {%1,%1};" : "=l"(xp) : "f"(xa[i]));
            int kk = k4 * 4 + i;
#pragma unroll
            for (int c = 0; c < 16; c++) {
                ulonglong2 w = Ws[kk * 16 + c];   // broadcast LDS.128
                asm("fma.rn.f32x2 %0, %1, %2, %0;" : "+l"(acc2[2*c])   : "l"(xp), "l"(w.x));
                asm("fma.rn.f32x2 %0, %1, %2, %0;" : "+l"(acc2[2*c+1]) : "l"(xp), "l"(w.y));
            }
        }
    }

    float s = 0.f, d = 0.f;
    unsigned hb[32];
#pragma unroll
    for (int c = 0; c < 32; c++) {
        float lo, hi;
        asm("mov.b64 {%0,%1}, %2;" : "=f"(lo), "=f"(hi) : "l"(acc2[c]));
        s += lo * atts[2*c] + hi * atts[2*c+1];
        d += lo * attd[2*c] + hi * attd[2*c+1];
        __nv_bfloat162 b = __floats2bfloat162_rn(lo, hi);
        hb[c] = *reinterpret_cast<unsigned*>(&b);
    }
    uint4* out4 = (uint4*)(g_hb + (size_t)node * 32);
#pragma unroll
    for (int q = 0; q < 8; q++)
        out4[q] = make_uint4(hb[4*q], hb[4*q+1], hb[4*q+2], hb[4*q+3]);
    g_as[node] = s;
    g_ad[node] = d;
}

// ---------------- kernel 7: scatter edges binned by dst (re-decode) ----------
__global__ void k_scatter(const int* __restrict__ ei, int E, int n) {
    int t2 = blockIdx.x * blockDim.x + threadIdx.x;
    int e = t2 * 2;
    if (e >= E) return;
    bool two = (e + 1 < E);
    int s0, d0, s1 = -1, d1 = -1;
    if (g_is64) {
        if (two && (E & 1) == 0) {
            int4 sv = ((const int4*)ei)[t2];
            int4 dv = ((const int4*)(ei + 2 * (size_t)E))[t2];
            s0 = sv.x; s1 = sv.z; d0 = dv.x; d1 = dv.z;
        } else {
            s0 = ei[2 * (size_t)e];
            d0 = ei[2 * ((size_t)E + e)];
            if (two) { s1 = ei[2 * (size_t)(e+1)]; d1 = ei[2 * ((size_t)E + e + 1)]; }
        }
    } else {
        if (two && (E & 1) == 0) {
            int2 sv = ((const int2*)ei)[t2];
            int2 dv = ((const int2*)(ei + (size_t)E))[t2];
            s0 = sv.x; s1 = sv.y; d0 = dv.x; d1 = dv.y;
        } else {
            s0 = ei[e];
            d0 = ei[(size_t)E + e];
            if (two) { s1 = ei[e+1]; d1 = ei[(size_t)E + e + 1]; }
        }
    }
    if ((unsigned)d0 < (unsigned)n) {
        int j = ((unsigned)s0 < (unsigned)n) ? s0 : 0;
        g_srt[atomicAdd(&g_cur[d0], 1)] = j;
    }
    if (two && (unsigned)d1 < (unsigned)n) {
        int j = ((unsigned)s1 < (unsigned)n) ? s1 : 0;
        g_srt[atomicAdd(&g_cur[d1], 1)] = j;
    }
}

// ---------------- kernel 8: warp-per-node aggregation + fused final ----------
// Chunk 32 edges: lane k loads (j, w) coalesced, shfl-broadcast for the bf16 h
// gather (128B/edge). Self loop = virtual edge. No max-shift (logits ~|8|,
// exp safe in fp32, softmax shift-invariant). Last block computes the output.
__global__ void __launch_bounds__(256) k_agg(
    const float* __restrict__ bias, int n,
    const float* __restrict__ Wl, const float* __restrict__ bl,
    float* __restrict__ out, float invn)
{
    __shared__ float rs[64];
    __shared__ int slast;
    int t = threadIdx.x;
    if (t < 64) rs[t] = 0.f;
    __syncthreads();

    int warp = (blockIdx.x * 256 + t) >> 5;
    int l = t & 31;
    if (warp < n) {
        int i = warp;
        int start = g_off[i];
        int len = g_count[i];
        float adi = g_ad[i];
        float accx = 0.f, accy = 0.f, den = 0.f;
        int total = len + 1;                       // + self loop
        for (int base = 0; base < total; base += 32) {
            int k = base + l;
            int j = i; float wv = 0.f;
            if (k < total) {
                if (k < len) j = g_srt[start + k];  // coalesced
                float v = g_as[j] + adi;
                v = v > 0.f ? v : 0.2f * v;
                wv = __expf(v);
            }
            den += wv;
            int m = total - base; if (m > 32) m = 32;
            if (m == 32) {
#pragma unroll
                for (int kk = 0; kk < 32; kk++) {
                    int jj  = __shfl_sync(0xffffffffu, j,  kk);
                    float w = __shfl_sync(0xffffffffu, wv, kk);
                    unsigned p = g_hb[(size_t)jj * 32 + l];
                    float2 hv = __bfloat1622float2(*reinterpret_cast<__nv_bfloat162*>(&p));
                    accx += w * hv.x;
                    accy += w * hv.y;
                }
            } else {
                for (int kk = 0; kk < m; kk++) {
                    int jj  = __shfl_sync(0xffffffffu, j,  kk);
                    float w = __shfl_sync(0xffffffffu, wv, kk);
                    unsigned p = g_hb[(size_t)jj * 32 + l];
                    float2 hv = __bfloat1622float2(*reinterpret_cast<__nv_bfloat162*>(&p));
                    accx += w * hv.x;
                    accy += w * hv.y;
                }
            }
        }
#pragma unroll
        for (int o = 16; o > 0; o >>= 1)
            den += __shfl_xor_sync(0xffffffffu, den, o);
        float inv = 1.f / den;
        float r0 = accx * inv + bias[2*l];     r0 = r0 > 0.f ? r0 : 0.f;
        float r1 = accy * inv + bias[2*l+1];   r1 = r1 > 0.f ? r1 : 0.f;
        atomicAdd(&rs[2*l],     r0);
        atomicAdd(&rs[2*l + 1], r1);
    }
    __syncthreads();
    if (t < 64) atomicAdd(&g_rsum[t], rs[t]);

    // last-block-done: fused final GEMV out = (rsum/N) @ W_lin + b_lin
    __threadfence();
    if (t == 0) {
        unsigned d = atomicAdd(&g_done, 1u);
        slast = (d == gridDim.x - 1) ? 1 : 0;
    }
    __syncthreads();
    if (slast && t < 64) {
        __threadfence();
        float s = 0.f;
#pragma unroll 4
        for (int c = 0; c < 64; c++) s += g_rsum[c] * Wl[c * 64 + t];
        out[t] = s * invn + bl[t];
    }
}

// ---------------- launcher ---------------------------------------------------
extern "C" void kernel_launch(void* const* d_in, const int* in_sizes, int n_in,
                              void* d_out, int out_size) {
    const float* x    = (const float*)d_in[0];
    const int*   ei   = (const int*)d_in[1];     // int32 OR int64 words (probed)
    const float* W    = (const float*)d_in[2];
    const float* atts = (const float*)d_in[3];
    const float* attd = (const float*)d_in[4];
    const float* bc   = (const float*)d_in[5];
    const float* Wl   = (const float*)d_in[6];
    const float* bl   = (const float*)d_in[7];
    float*       out  = (float*)d_out;

    int n = in_sizes[0] / 128;   // nodes
    int E = in_sizes[1] / 2;     // edges ([2, E] layout)
    if (n > N_MAX) n = N_MAX;
    if (E > E_MAX) E = E_MAX;

    int nb1 = (n + 1023) / 1024;
    int Epairs = (E + 1) / 2;

    k_init   <<<(n + 255) / 256, 256>>>(ei, E, n);
    k_hist   <<<(Epairs + 255) / 256, 256>>>(ei, E, n);
    k_scan1  <<<nb1, 1024>>>(n);
    k_gemm   <<<(n + 127) / 128, 128>>>(x, W, atts, attd, n);   // launch #4 -> profiled
    k_scan2  <<<1, 256>>>(nb1);
    k_scan3  <<<(n + 255) / 256, 256>>>(n);
    k_scatter<<<(Epairs + 255) / 256, 256>>>(ei, E, n);
    k_agg    <<<(n + 7) / 8, 256>>>(bc, n, Wl, bl, out, 1.f / (float)n);
}